// round 14
// baseline (speedup 1.0000x reference)
#include <cuda_runtime.h>
#include <cuda_bf16.h>
#include <math.h>
#include <stdint.h>

#define BB 32
#define NN 1024
#define KNN 20
#define RTOT (BB*NN)          // 32768 rows
#define NEG_SLOPE 0.2f
#define EPS 1e-5f

// ---------------- static scratch (allocation-free rule) ----------------
__device__ __align__(256) float g_pd[(size_t)BB*NN*NN];     // 128 MB
__device__ __align__(256) int   g_idx[(size_t)RTOT*KNN];
__device__ __align__(256) float g_pq[(size_t)RTOT*512];     // packed [p|q]
__device__ __align__(256) float g_hmax[(size_t)RTOT*256];
__device__ __align__(256) float g_wc[1024];                 // layer-1 packed W (fp32)
__device__ __align__(256) float g_wch[131072];              // tf32-hi packed W, layers 2-4
__device__ __align__(256) float g_wcl[131072];              // tf32-lo
__device__ __align__(256) float g_fh[(size_t)RTOT*128];     // tf32-hi features
__device__ __align__(256) float g_fl[(size_t)RTOT*128];
__device__ __align__(256) __nv_bfloat16 g_c5h[(size_t)RTOT*512];  // bf16-hi cat
__device__ __align__(256) __nv_bfloat16 g_c5l[(size_t)RTOT*512];  // bf16-lo cat
__device__ __align__(256) float g_xx[RTOT];
__device__ __align__(256) float g_sum[1024];
__device__ __align__(256) float g_sumsq[1024];
__device__ __align__(256) float g_sum5[1024];
__device__ __align__(256) float g_sumsq5[1024];
__device__ __align__(256) float g_redp[BB*8*1024];          // layer-5 partial maxes
__device__ __align__(256) __nv_bfloat16 g_w5h[1024*512];
__device__ __align__(256) __nv_bfloat16 g_w5l[1024*512];

// ---------------- mma helpers ----------------
__device__ __forceinline__ void mma16816(float* c, const uint32_t* a, const uint32_t* b) {
    asm volatile("mma.sync.aligned.m16n8k16.row.col.f32.bf16.bf16.f32 "
        "{%0,%1,%2,%3}, {%4,%5,%6,%7}, {%8,%9}, {%0,%1,%2,%3};"
        : "+f"(c[0]), "+f"(c[1]), "+f"(c[2]), "+f"(c[3])
        : "r"(a[0]), "r"(a[1]), "r"(a[2]), "r"(a[3]), "r"(b[0]), "r"(b[1]));
}
__device__ __forceinline__ void mma1688(float* c, const uint32_t* a, const uint32_t* b) {
    asm volatile("mma.sync.aligned.m16n8k8.row.col.f32.tf32.tf32.f32 "
        "{%0,%1,%2,%3}, {%4,%5,%6,%7}, {%8,%9}, {%0,%1,%2,%3};"
        : "+f"(c[0]), "+f"(c[1]), "+f"(c[2]), "+f"(c[3])
        : "r"(a[0]), "r"(a[1]), "r"(a[2]), "r"(a[3]), "r"(b[0]), "r"(b[1]));
}
__device__ __forceinline__ void split_tf32(float v, uint32_t &hi, uint32_t &lo) {
    asm("cvt.rna.tf32.f32 %0, %1;" : "=r"(hi) : "f"(v));
    float r = v - __uint_as_float(hi);
    asm("cvt.rna.tf32.f32 %0, %1;" : "=r"(lo) : "f"(r));
}

// ---------------- TF32x3 tile engine: 128x128 C tile, 256 threads ----------------
// Fragment-major smem staging: per-thread mma fragments are CONTIGUOUS, so
// compute loads are LDS.128 (A: a0..a3) and LDS.64 (B: b0,b1).
//
// A layout (128 rows x 32 k): word(r,c) = (((r>>4)*4 + (c>>3))*32 + (r&7)*4 + (c&3))*4
//                                         + ((r>>3)&1) + 2*((c>>2)&1)
// B layout (128 rows x 32 k): word(n,c) = ((n>>3)*4 + (c>>3))*64 + (n&7)*8 + (c&3)*2
//                                         + ((c>>2)&1)
// Each 128x32 chunk = 4096 words = 16 KB; 4 buffers (A/B x hi/lo) = 64 KB.
#define SMCHUNK 4096
#define SMT32_BYTES (4*SMCHUNK*4)

__device__ __forceinline__ void t32_stage_A(const float* __restrict__ Ph,
                                            const float* __restrict__ Pl, int ldp,
                                            int kc, uint32_t* sh, uint32_t* sl, int tid) {
    #pragma unroll
    for (int it = 0; it < 4; it++) {
        int i = it*256 + tid;
        int row = i >> 3, kq = (i & 7)*4;
        uint4 h = *(const uint4*)(Ph + (size_t)row*ldp + kc + kq);
        uint4 l = *(const uint4*)(Pl + (size_t)row*ldp + kc + kq);
        int base = (((row>>4)*4 + (kq>>3))*32 + (row&7)*4)*4
                   + ((row>>3)&1) + 2*((kq>>2)&1);
        sh[base] = h.x; sh[base+4] = h.y; sh[base+8] = h.z; sh[base+12] = h.w;
        sl[base] = l.x; sl[base+4] = l.y; sl[base+8] = l.z; sl[base+12] = l.w;
    }
}

__device__ __forceinline__ void t32_stage_B(const float* __restrict__ Ph,
                                            const float* __restrict__ Pl, int ldp,
                                            int kc, uint32_t* sh, uint32_t* sl, int tid) {
    #pragma unroll
    for (int it = 0; it < 4; it++) {
        int i = it*256 + tid;
        int row = i >> 3, kq = (i & 7)*4;
        uint4 h = *(const uint4*)(Ph + (size_t)row*ldp + kc + kq);
        uint4 l = *(const uint4*)(Pl + (size_t)row*ldp + kc + kq);
        int base = ((row>>3)*4 + (kq>>3))*64 + (row&7)*8 + ((kq>>2)&1);
        sh[base] = h.x; sh[base+2] = h.y; sh[base+4] = h.z; sh[base+6] = h.w;
        sl[base] = l.x; sl[base+2] = l.y; sl[base+4] = l.z; sl[base+6] = l.w;
    }
}

__device__ __forceinline__ void t32_tile(const float* __restrict__ Ah_g, const float* __restrict__ Al_g, int lda,
                                         const float* __restrict__ Bh_g, const float* __restrict__ Bl_g, int ldb,
                                         int Kdim,
                                         uint32_t* sAh, uint32_t* sAl, uint32_t* sBh, uint32_t* sBl,
                                         int tid, float (&acc)[4][4][4]) {
    int warp = tid >> 5, lane = tid & 31;
    int wm = (warp >> 2)*64, wn = (warp & 3)*32;
    int rbb = wm >> 4;      // 0 or 4
    int nbb = wn >> 3;      // 0,4,8,12
    for (int kc = 0; kc < Kdim; kc += 32) {
        t32_stage_A(Ah_g, Al_g, lda, kc, sAh, sAl, tid);
        t32_stage_B(Bh_g, Bl_g, ldb, kc, sBh, sBl, tid);
        __syncthreads();
        #pragma unroll
        for (int kb = 0; kb < 4; kb++) {
            uint4 ah[4], al[4];
            #pragma unroll
            for (int mt = 0; mt < 4; mt++) {
                int off = (((rbb + mt)*4 + kb)*32 + lane)*4;
                ah[mt] = *(const uint4*)(sAh + off);
                al[mt] = *(const uint4*)(sAl + off);
            }
            #pragma unroll
            for (int nt = 0; nt < 4; nt++) {
                int off = ((nbb + nt)*4 + kb)*64 + lane*2;
                uint2 bh = *(const uint2*)(sBh + off);
                uint2 bl = *(const uint2*)(sBl + off);
                #pragma unroll
                for (int mt = 0; mt < 4; mt++) {
                    mma1688(acc[mt][nt], (const uint32_t*)&ah[mt], (const uint32_t*)&bh);
                    mma1688(acc[mt][nt], (const uint32_t*)&ah[mt], (const uint32_t*)&bl);
                    mma1688(acc[mt][nt], (const uint32_t*)&al[mt], (const uint32_t*)&bh);
                }
            }
        }
        __syncthreads();
    }
}

__global__ void __launch_bounds__(256)
k_pair_t32(const float* __restrict__ fh, const float* __restrict__ fl, int Kdim,
           const float* __restrict__ xx, float* __restrict__ pd) {
    extern __shared__ uint32_t sm32[];
    uint32_t* sAh = sm32;
    uint32_t* sAl = sm32 + SMCHUNK;
    uint32_t* sBh = sm32 + 2*SMCHUNK;
    uint32_t* sBl = sm32 + 3*SMCHUNK;
    int b = blockIdx.z;
    const float* Fh = fh + (size_t)b*NN*Kdim;
    const float* Fl = fl + (size_t)b*NN*Kdim;
    const float* xb = xx + b*NN;
    int n0 = blockIdx.x*128, m0 = blockIdx.y*128;
    int tid = threadIdx.x;
    float acc[4][4][4];
    #pragma unroll
    for (int i = 0; i < 4; i++)
        #pragma unroll
        for (int j = 0; j < 4; j++)
            #pragma unroll
            for (int r = 0; r < 4; r++) acc[i][j][r] = 0.f;

    t32_tile(Fh + (size_t)n0*Kdim, Fl + (size_t)n0*Kdim, Kdim,
             Fh + (size_t)m0*Kdim, Fl + (size_t)m0*Kdim, Kdim, Kdim,
             sAh, sAl, sBh, sBl, tid, acc);

    int warp = tid >> 5, lane = tid & 31;
    int g = lane >> 2, t = lane & 3;
    int wm = (warp >> 2)*64, wn = (warp & 3)*32;
    float* pb = pd + (size_t)b*NN*NN;
    #pragma unroll
    for (int mt = 0; mt < 4; mt++) {
        int n = n0 + wm + mt*16 + g;
        float xn0 = xb[n], xn1 = xb[n+8];
        #pragma unroll
        for (int nt = 0; nt < 4; nt++) {
            int col = m0 + wn + nt*8 + 2*t;
            float xm0 = xb[col], xm1 = xb[col+1];
            *(float2*)(pb + (size_t)n*NN + col) =
                make_float2(2.f*acc[mt][nt][0] - xn0 - xm0, 2.f*acc[mt][nt][1] - xn0 - xm1);
            *(float2*)(pb + (size_t)(n+8)*NN + col) =
                make_float2(2.f*acc[mt][nt][2] - xn1 - xm0, 2.f*acc[mt][nt][3] - xn1 - xm1);
        }
    }
}

__global__ void __launch_bounds__(256)
k_pq_t32(const float* __restrict__ fh, const float* __restrict__ fl, int lda,
         const float* __restrict__ wh, const float* __restrict__ wl, int ldb,
         float* __restrict__ Cout, int ldc, int Kdim) {
    extern __shared__ uint32_t sm32[];
    uint32_t* sAh = sm32;
    uint32_t* sAl = sm32 + SMCHUNK;
    uint32_t* sBh = sm32 + 2*SMCHUNK;
    uint32_t* sBl = sm32 + 3*SMCHUNK;
    int m0 = blockIdx.x*128, o0 = blockIdx.y*128;
    int tid = threadIdx.x;
    float acc[4][4][4];
    #pragma unroll
    for (int i = 0; i < 4; i++)
        #pragma unroll
        for (int j = 0; j < 4; j++)
            #pragma unroll
            for (int r = 0; r < 4; r++) acc[i][j][r] = 0.f;

    t32_tile(fh + (size_t)m0*lda, fl + (size_t)m0*lda, lda,
             wh + (size_t)o0*ldb, wl + (size_t)o0*ldb, ldb, Kdim,
             sAh, sAl, sBh, sBl, tid, acc);

    int warp = tid >> 5, lane = tid & 31;
    int g = lane >> 2, t = lane & 3;
    int wm = (warp >> 2)*64, wn = (warp & 3)*32;
    #pragma unroll
    for (int mt = 0; mt < 4; mt++) {
        int r = m0 + wm + mt*16 + g;
        #pragma unroll
        for (int nt = 0; nt < 4; nt++) {
            int col = o0 + wn + nt*8 + 2*t;
            *(float2*)(Cout + (size_t)r*ldc + col)     = make_float2(acc[mt][nt][0], acc[mt][nt][1]);
            *(float2*)(Cout + (size_t)(r+8)*ldc + col) = make_float2(acc[mt][nt][2], acc[mt][nt][3]);
        }
    }
}

// ---------------- warp top-20 over 32x32 register tile ----------------
__device__ __forceinline__ void warp_top20(float (&vals)[32], int lane, int* orow) {
    unsigned rm = 0;
    float bv = vals[0]; int bslot = 0;
    #pragma unroll
    for (int j = 1; j < 32; j++) { float v = vals[j]; if (v > bv) { bv = v; bslot = j; } }
    for (int it = 0; it < KNN; it++) {
        float cv = bv;
        int ci = (bslot >= 0) ? (bslot*32 + lane) : 0x7fffffff;
        if (bslot < 0) cv = -INFINITY;
        #pragma unroll
        for (int s = 16; s > 0; s >>= 1) {
            float ov = __shfl_xor_sync(0xffffffffu, cv, s);
            int   oi = __shfl_xor_sync(0xffffffffu, ci, s);
            if (ov > cv || (ov == cv && oi < ci)) { cv = ov; ci = oi; }
        }
        if (lane == 0) orow[it] = ci;
        if ((ci & 31) == lane) {
            rm |= 1u << (ci >> 5);
            bv = -INFINITY; bslot = -1;
            #pragma unroll
            for (int j = 0; j < 32; j++) {
                if (!((rm >> j) & 1u)) {
                    float v = vals[j];
                    if (v > bv) { bv = v; bslot = j; }
                }
            }
        }
    }
}

// ---------------- kernels ----------------

__global__ void k_knn3(const float* __restrict__ x, int* __restrict__ idx,
                       float* __restrict__ sum, float* __restrict__ sumsq,
                       float* __restrict__ sum5, float* __restrict__ sumsq5) {
    __shared__ float sx[NN], sy[NN], sz[NN];
    int b = blockIdx.y;
    const float* xb = x + (size_t)b*NN*3;
    int tid = threadIdx.x;
    if (blockIdx.x == 0 && b == 0) {
        for (int i = tid; i < 1024; i += 256) {
            sum[i] = 0.f; sumsq[i] = 0.f; sum5[i] = 0.f; sumsq5[i] = 0.f;
        }
    }
    for (int i = tid; i < NN; i += 256) {
        sx[i] = xb[i*3+0]; sy[i] = xb[i*3+1]; sz[i] = xb[i*3+2];
    }
    __syncthreads();
    int warp = tid >> 5, lane = tid & 31;
    int n = blockIdx.x*8 + warp;
    float xnx = sx[n], xny = sy[n], xnz = sz[n];
    float xxn = xnx*xnx; xxn += xny*xny; xxn += xnz*xnz;
    float vals[32];
    #pragma unroll
    for (int j = 0; j < 32; j++) {
        int m = j*32 + lane;
        float mx = sx[m], my = sy[m], mz = sz[m];
        float inner = xnx*mx; inner += xny*my; inner += xnz*mz;
        float xxm = mx*mx; xxm += my*my; xxm += mz*mz;
        vals[j] = 2.f*inner - xxn - xxm;
    }
    warp_top20(vals, lane, idx + (size_t)(b*NN + n)*KNN);
}

__global__ void k_topk_w(const float* __restrict__ pd, int* __restrict__ idx,
                         float* __restrict__ sum, float* __restrict__ sumsq) {
    int tid = threadIdx.x;
    if (blockIdx.x == 0) {
        for (int i = tid; i < 1024; i += 256) { sum[i] = 0.f; sumsq[i] = 0.f; }
    }
    int warp = tid >> 5;
    int lane = tid & 31;
    int row = blockIdx.x*8 + warp;
    const float* prow = pd + (size_t)row*NN;
    float vals[32];
    #pragma unroll
    for (int j = 0; j < 32; j++) vals[j] = prow[j*32 + lane];
    warp_top20(vals, lane, idx + (size_t)row*KNN);
}

__global__ void k_wpack(const float* __restrict__ W, int C, int O, float* __restrict__ wc) {
    int i = blockIdx.x*blockDim.x + threadIdx.x;
    if (i >= 2*O*C) return;
    int o2 = i / C, c = i - o2*C;
    if (o2 < O) wc[i] = W[(size_t)o2*2*C + c];
    else {
        int o = o2 - O;
        wc[i] = W[(size_t)o*2*C + C + c] - W[(size_t)o*2*C + c];
    }
}

__global__ void k_wpack_t32(const float* __restrict__ W, int C, int O,
                            float* __restrict__ wh, float* __restrict__ wl) {
    int i = blockIdx.x*blockDim.x + threadIdx.x;
    if (i >= 2*O*C) return;
    int o2 = i / C, c = i - o2*C;
    float v;
    if (o2 < O) v = W[(size_t)o2*2*C + c];
    else {
        int o = o2 - O;
        v = W[(size_t)o*2*C + C + c] - W[(size_t)o*2*C + c];
    }
    uint32_t hi, lo;
    split_tf32(v, hi, lo);
    wh[i] = __uint_as_float(hi);
    wl[i] = __uint_as_float(lo);
}

__global__ void k_cvt_w5(const float* __restrict__ W5, __nv_bfloat16* __restrict__ wh,
                         __nv_bfloat16* __restrict__ wl) {
    int i = blockIdx.x*blockDim.x + threadIdx.x;
    if (i >= 1024*512) return;
    float w = W5[i];
    __nv_bfloat16 h = __float2bfloat16(w);
    wh[i] = h;
    wl[i] = __float2bfloat16(w - __bfloat162float(h));
}

__global__ void k_sgemm(const float* __restrict__ A, int lda,
                        const float* __restrict__ Bw, int ldb,
                        float* __restrict__ Cout, int Kdim, int O) {
    __shared__ float As[16][65], Ws[16][65];
    int tx = threadIdx.x, ty = threadIdx.y;
    int tid = ty*16 + tx;
    int m0 = blockIdx.x*64, o0 = blockIdx.y*64;
    float acc[4][4];
    #pragma unroll
    for (int i = 0; i < 4; i++)
        #pragma unroll
        for (int j = 0; j < 4; j++) acc[i][j] = 0.f;
    for (int k0 = 0; k0 < Kdim; k0 += 16) {
        #pragma unroll
        for (int r = 0; r < 4; r++) {
            int i  = tid + r*256;
            int kk = i & 15, mm = i >> 4;
            As[kk][mm] = (k0+kk < Kdim) ? A[(size_t)(m0+mm)*lda + k0+kk] : 0.f;
            Ws[kk][mm] = (k0+kk < Kdim) ? Bw[(size_t)(o0+mm)*ldb + k0+kk] : 0.f;
        }
        __syncthreads();
        #pragma unroll
        for (int kk = 0; kk < 16; kk++) {
            float a[4], bfr[4];
            #pragma unroll
            for (int i = 0; i < 4; i++) a[i] = As[kk][ty*4 + i];
            #pragma unroll
            for (int j = 0; j < 4; j++) bfr[j] = Ws[kk][tx*4 + j];
            #pragma unroll
            for (int i = 0; i < 4; i++)
                #pragma unroll
                for (int j = 0; j < 4; j++) acc[i][j] += a[i]*bfr[j];
        }
        __syncthreads();
    }
    #pragma unroll
    for (int i = 0; i < 4; i++)
        #pragma unroll
        for (int j = 0; j < 4; j++)
            Cout[(size_t)(m0 + ty*4 + i)*O + o0 + tx*4 + j] = acc[i][j];
}

// ---------------- layer-5 GEMM with FUSED max/sum/sumsq reduction ----
#define KC5 64
#define SA5 72
#define SM5_TILE (128*SA5)
#define SM5_BYTES (4*SM5_TILE*2)

__global__ void __launch_bounds__(256, 1)
k_mma5(const __nv_bfloat16* __restrict__ c5h, const __nv_bfloat16* __restrict__ c5l,
       const __nv_bfloat16* __restrict__ w5h, const __nv_bfloat16* __restrict__ w5l,
       float* __restrict__ redp, float* __restrict__ sum5, float* __restrict__ sumsq5) {
    extern __shared__ __nv_bfloat16 sm[];
    __nv_bfloat16* Ah = sm;
    __nv_bfloat16* Al = sm + SM5_TILE;
    __nv_bfloat16* Bh = sm + 2*SM5_TILE;
    __nv_bfloat16* Bl = sm + 3*SM5_TILE;

    int tid = threadIdx.x;
    int warp = tid >> 5, lane = tid & 31;
    int g = lane >> 2, t = lane & 3;
    int m0 = blockIdx.x*128, o0 = blockIdx.y*128;
    int wm = (warp >> 2)*64;
    int wn = (warp & 3)*32;

    float acc[4][4][4];
    #pragma unroll
    for (int i = 0; i < 4; i++)
        #pragma unroll
        for (int j = 0; j < 4; j++)
            #pragma unroll
            for (int r = 0; r < 4; r++) acc[i][j][r] = 0.f;

    for (int kc = 0; kc < 512; kc += KC5) {
        #pragma unroll
        for (int it = 0; it < 4; it++) {
            int i = it*256 + tid;
            int row = i >> 3, kq = (i & 7)*8;
            uint4 h = *(const uint4*)(c5h + (size_t)(m0+row)*512 + kc + kq);
            uint4 l = *(const uint4*)(c5l + (size_t)(m0+row)*512 + kc + kq);
            *(uint4*)(Ah + row*SA5 + kq) = h;
            *(uint4*)(Al + row*SA5 + kq) = l;
        }
        #pragma unroll
        for (int it = 0; it < 4; it++) {
            int i = it*256 + tid;
            int row = i >> 3, kq = (i & 7)*8;
            uint4 h = *(const uint4*)(w5h + (size_t)(o0+row)*512 + kc + kq);
            uint4 l = *(const uint4*)(w5l + (size_t)(o0+row)*512 + kc + kq);
            *(uint4*)(Bh + row*SA5 + kq) = h;
            *(uint4*)(Bl + row*SA5 + kq) = l;
        }
        __syncthreads();

        #pragma unroll
        for (int ks = 0; ks < KC5; ks += 16) {
            uint32_t ah[4][4], al[4][4];
            #pragma unroll
            for (int mt = 0; mt < 4; mt++) {
                int r = wm + mt*16;
                ah[mt][0] = *(const uint32_t*)(Ah + (r+g  )*SA5 + ks + 2*t);
                ah[mt][1] = *(const uint32_t*)(Ah + (r+g+8)*SA5 + ks + 2*t);
                ah[mt][2] = *(const uint32_t*)(Ah + (r+g  )*SA5 + ks + 2*t + 8);
                ah[mt][3] = *(const uint32_t*)(Ah + (r+g+8)*SA5 + ks + 2*t + 8);
                al[mt][0] = *(const uint32_t*)(Al + (r+g  )*SA5 + ks + 2*t);
                al[mt][1] = *(const uint32_t*)(Al + (r+g+8)*SA5 + ks + 2*t);
                al[mt][2] = *(const uint32_t*)(Al + (r+g  )*SA5 + ks + 2*t + 8);
                al[mt][3] = *(const uint32_t*)(Al + (r+g+8)*SA5 + ks + 2*t + 8);
            }
            #pragma unroll
            for (int nt = 0; nt < 4; nt++) {
                int nr = wn + nt*8 + g;
                uint32_t bh[2], bl[2];
                bh[0] = *(const uint32_t*)(Bh + nr*SA5 + ks + 2*t);
                bh[1] = *(const uint32_t*)(Bh + nr*SA5 + ks + 2*t + 8);
                bl[0] = *(const uint32_t*)(Bl + nr*SA5 + ks + 2*t);
                bl[1] = *(const uint32_t*)(Bl + nr*SA5 + ks + 2*t + 8);
                #pragma unroll
                for (int mt = 0; mt < 4; mt++) {
                    mma16816(acc[mt][nt], ah[mt], bh);
                    mma16816(acc[mt][nt], ah[mt], bl);
                    mma16816(acc[mt][nt], al[mt], bh);
                }
            }
        }
        __syncthreads();
    }

    // fused reduction over this block's 128 rows x 128 cols
    float cmax[4][2], csum[4][2], csq[4][2];
    #pragma unroll
    for (int nt = 0; nt < 4; nt++)
        #pragma unroll
        for (int p = 0; p < 2; p++) { cmax[nt][p] = -INFINITY; csum[nt][p] = 0.f; csq[nt][p] = 0.f; }
    #pragma unroll
    for (int mt = 0; mt < 4; mt++)
        #pragma unroll
        for (int nt = 0; nt < 4; nt++) {
            float v0 = acc[mt][nt][0], v1 = acc[mt][nt][1];
            float v2 = acc[mt][nt][2], v3 = acc[mt][nt][3];
            cmax[nt][0] = fmaxf(cmax[nt][0], fmaxf(v0, v2));
            cmax[nt][1] = fmaxf(cmax[nt][1], fmaxf(v1, v3));
            csum[nt][0] += v0 + v2;  csum[nt][1] += v1 + v3;
            csq[nt][0]  += v0*v0 + v2*v2;  csq[nt][1] += v1*v1 + v3*v3;
        }
    #pragma unroll
    for (int s = 4; s <= 16; s <<= 1) {
        #pragma unroll
        for (int nt = 0; nt < 4; nt++)
            #pragma unroll
            for (int p = 0; p < 2; p++) {
                cmax[nt][p] = fmaxf(cmax[nt][p], __shfl_xor_sync(0xffffffffu, cmax[nt][p], s));
                csum[nt][p] += __shfl_xor_sync(0xffffffffu, csum[nt][p], s);
                csq[nt][p]  += __shfl_xor_sync(0xffffffffu, csq[nt][p], s);
            }
    }
    float* rr = (float*)sm;
    float* rmax = rr;
    float* rsum = rr + 256;
    float* rsq  = rr + 512;
    int wrow = warp >> 2;
    if (g == 0) {
        #pragma unroll
        for (int nt = 0; nt < 4; nt++)
            #pragma unroll
            for (int p = 0; p < 2; p++) {
                int col = wn + nt*8 + 2*t + p;
                rmax[wrow*128 + col] = cmax[nt][p];
                rsum[wrow*128 + col] = csum[nt][p];
                rsq[wrow*128 + col]  = csq[nt][p];
            }
    }
    __syncthreads();
    if (tid < 128) {
        float m = fmaxf(rmax[tid], rmax[128 + tid]);
        float s = rsum[tid] + rsum[128 + tid];
        float q = rsq[tid] + rsq[128 + tid];
        int b = blockIdx.x >> 3, mb = blockIdx.x & 7;
        redp[((size_t)b*8 + mb)*1024 + o0 + tid] = m;
        atomicAdd(&sum5[o0 + tid], s);
        atomicAdd(&sumsq5[o0 + tid], q);
    }
}

// gather: 256 threads, float4 column groups, 32 rows/block
__global__ void __launch_bounds__(256)
k_gather(const float* __restrict__ pq, const int* __restrict__ idx,
         float* __restrict__ hmax,
         float* __restrict__ sum, float* __restrict__ sumsq, int O) {
    int tid = threadIdx.x;
    int oq4 = O >> 2;
    int nr = 256/oq4;
    int rsub = tid / oq4;
    int cg = tid - rsub*oq4;
    int r0 = blockIdx.x*32;
    int b = r0 >> 10;
    int ld = 2*O;
    __shared__ int sidx[32*KNN];
    __shared__ float4 ssum[256], ssq[256];
    for (int i = tid; i < 32*KNN; i += 256) sidx[i] = idx[(size_t)r0*KNN + i];
    __syncthreads();
    const float* pb = pq + (size_t)b*NN*ld;
    float4 s  = make_float4(0.f, 0.f, 0.f, 0.f);
    float4 s2 = make_float4(0.f, 0.f, 0.f, 0.f);
    for (int n = rsub; n < 32; n += nr) {
        int row = r0 + n;
        float4 cq = *(const float4*)(pq + (size_t)row*ld + O + cg*4);
        float4 mx = make_float4(-INFINITY, -INFINITY, -INFINITY, -INFINITY);
        #pragma unroll
        for (int k = 0; k < KNN; k++) {
            float4 v = *(const float4*)(pb + (size_t)sidx[n*KNN + k]*ld + cg*4);
            mx.x = fmaxf(mx.x, v.x); mx.y = fmaxf(mx.y, v.y);
            mx.z = fmaxf(mx.z, v.z); mx.w = fmaxf(mx.w, v.w);
            float hx = v.x + cq.x, hy = v.y + cq.y, hz = v.z + cq.z, hw = v.w + cq.w;
            s.x += hx; s.y += hy; s.z += hz; s.w += hw;
            s2.x += hx*hx; s2.y += hy*hy; s2.z += hz*hz; s2.w += hw*hw;
        }
        *(float4*)(hmax + (size_t)row*O + cg*4) =
            make_float4(mx.x + cq.x, mx.y + cq.y, mx.z + cq.z, mx.w + cq.w);
    }
    ssum[tid] = s; ssq[tid] = s2;
    __syncthreads();
    if (rsub == 0) {
        for (int j = 1; j < nr; j++) {
            float4 a = ssum[j*oq4 + cg], q = ssq[j*oq4 + cg];
            s.x += a.x; s.y += a.y; s.z += a.z; s.w += a.w;
            s2.x += q.x; s2.y += q.y; s2.z += q.z; s2.w += q.w;
        }
        atomicAdd(&sum[cg*4+0], s.x);  atomicAdd(&sum[cg*4+1], s.y);
        atomicAdd(&sum[cg*4+2], s.z);  atomicAdd(&sum[cg*4+3], s.w);
        atomicAdd(&sumsq[cg*4+0], s2.x); atomicAdd(&sumsq[cg*4+1], s2.y);
        atomicAdd(&sumsq[cg*4+2], s2.z); atomicAdd(&sumsq[cg*4+3], s2.w);
    }
}

__global__ void k_bn_f(const float* __restrict__ hmax, const float* __restrict__ sum,
                       const float* __restrict__ sumsq,
                       const float* __restrict__ gamma, const float* __restrict__ beta,
                       __nv_bfloat16* __restrict__ c5h, __nv_bfloat16* __restrict__ c5l, int coff,
                       float* __restrict__ fh, float* __restrict__ fl, float* __restrict__ xx,
                       int O, float invCnt, int wantNext) {
    int warp = threadIdx.x >> 5, lane = threadIdx.x & 31;
    int row = blockIdx.x*8 + warp;
    float s2 = 0.f;
    for (int o = lane; o < O; o += 32) {
        float mean = sum[o]*invCnt;
        float var  = sumsq[o]*invCnt - mean*mean;
        float hn = (hmax[(size_t)row*O + o] - mean)*rsqrtf(var + EPS)*gamma[o] + beta[o];
        hn = hn >= 0.f ? hn : NEG_SLOPE*hn;
        __nv_bfloat16 h = __float2bfloat16(hn);
        c5h[(size_t)row*512 + coff + o] = h;
        c5l[(size_t)row*512 + coff + o] = __float2bfloat16(hn - __bfloat162float(h));
        if (wantNext) {
            uint32_t thi, tlo;
            split_tf32(hn, thi, tlo);
            fh[(size_t)row*O + o] = __uint_as_float(thi);
            fl[(size_t)row*O + o] = __uint_as_float(tlo);
            s2 += hn*hn;
        }
    }
    if (wantNext) {
        #pragma unroll
        for (int s = 16; s > 0; s >>= 1) s2 += __shfl_xor_sync(0xffffffffu, s2, s);
        if (lane == 0) xx[row] = s2;
    }
}

__global__ void k_final(const float* __restrict__ redp, const float* __restrict__ sum,
                        const float* __restrict__ sumsq,
                        const float* __restrict__ gamma, const float* __restrict__ beta,
                        float* __restrict__ out) {
    int e = blockIdx.x*blockDim.x + threadIdx.x;   // 32768
    int b = e >> 10, o = e & 1023;
    float mx = -INFINITY;
    #pragma unroll
    for (int z = 0; z < 8; z++) mx = fmaxf(mx, redp[((size_t)b*8 + z)*1024 + o]);
    float invCnt = 1.f/32768.f;
    float mean = sum[o]*invCnt;
    float var  = sumsq[o]*invCnt - mean*mean;
    float hn = (mx - mean)*rsqrtf(var + EPS)*gamma[o] + beta[o];
    out[e] = hn >= 0.f ? hn : NEG_SLOPE*hn;
}

// ---------------- host driver ----------------

extern "C" void kernel_launch(void* const* d_in, const int* in_sizes, int n_in,
                              void* d_out, int out_size) {
    const float* x = (const float*)d_in[0];
    const float* W[5]; const float* ga[5]; const float* be[5];
    for (int i = 0; i < 5; i++) {
        W[i]  = (const float*)d_in[1 + 3*i];
        ga[i] = (const float*)d_in[2 + 3*i];
        be[i] = (const float*)d_in[3 + 3*i];
    }

    float *pd, *pq, *hmax, *wc, *wch, *wcl, *fh, *fl, *xx, *sum, *sumsq, *sum5, *sumsq5, *redp;
    __nv_bfloat16 *c5h, *c5l, *w5h, *w5l;
    int *idx;
    cudaGetSymbolAddress((void**)&pd,    g_pd);
    cudaGetSymbolAddress((void**)&idx,   g_idx);
    cudaGetSymbolAddress((void**)&pq,    g_pq);
    cudaGetSymbolAddress((void**)&hmax,  g_hmax);
    cudaGetSymbolAddress((void**)&wc,    g_wc);
    cudaGetSymbolAddress((void**)&wch,   g_wch);
    cudaGetSymbolAddress((void**)&wcl,   g_wcl);
    cudaGetSymbolAddress((void**)&fh,    g_fh);
    cudaGetSymbolAddress((void**)&fl,    g_fl);
    cudaGetSymbolAddress((void**)&xx,    g_xx);
    cudaGetSymbolAddress((void**)&sum,   g_sum);
    cudaGetSymbolAddress((void**)&sumsq, g_sumsq);
    cudaGetSymbolAddress((void**)&sum5,  g_sum5);
    cudaGetSymbolAddress((void**)&sumsq5, g_sumsq5);
    cudaGetSymbolAddress((void**)&redp,  g_redp);
    cudaGetSymbolAddress((void**)&c5h,   g_c5h);
    cudaGetSymbolAddress((void**)&c5l,   g_c5l);
    cudaGetSymbolAddress((void**)&w5h,   g_w5h);
    cudaGetSymbolAddress((void**)&w5l,   g_w5l);

    cudaFuncSetAttribute(k_mma5, cudaFuncAttributeMaxDynamicSharedMemorySize, SM5_BYTES);
    cudaFuncSetAttribute(k_pair_t32, cudaFuncAttributeMaxDynamicSharedMemorySize, SMT32_BYTES);
    cudaFuncSetAttribute(k_pq_t32, cudaFuncAttributeMaxDynamicSharedMemorySize, SMT32_BYTES);

    float* wch2 = wch;           float* wcl2 = wcl;
    float* wch3 = wch + 8192;    float* wcl3 = wcl + 8192;
    float* wch4 = wch + 24576;   float* wcl4 = wcl + 24576;

    const float invKN = 1.f/((float)RTOT*KNN);

    // ---- layer 1 (C=3) ----
    k_wpack<<<(2*64*3 + 255)/256, 256>>>(W[0], 3, 64, wc);
    k_knn3<<<dim3(128, 32), 256>>>(x, idx, sum, sumsq, sum5, sumsq5);
    k_sgemm<<<dim3(RTOT/64, 2), dim3(16,16)>>>(x, 3, wc, 3, pq, 3, 128);
    k_gather<<<RTOT/32, 256>>>(pq, idx, hmax, sum, sumsq, 64);
    k_bn_f<<<RTOT/8, 256>>>(hmax, sum, sumsq, ga[0], be[0],
                            c5h, c5l, 0, fh, fl, xx, 64, invKN, 1);

    // ---- layer 2 ----
    k_pair_t32<<<dim3(8, 8, 32), 256, SMT32_BYTES>>>(fh, fl, 64, xx, pd);
    k_wpack_t32<<<(2*64*64  + 255)/256, 256>>>(W[1], 64,  64,  wch2, wcl2);
    k_wpack_t32<<<(2*128*64 + 255)/256, 256>>>(W[2], 64,  128, wch3, wcl3);
    k_wpack_t32<<<(2*256*128+ 255)/256, 256>>>(W[3], 128, 256, wch4, wcl4);
    k_cvt_w5<<<(1024*512 + 255)/256, 256>>>(W[4], w5h, w5l);
    k_topk_w<<<RTOT/8, 256>>>(pd, idx, sum, sumsq);
    k_pq_t32<<<dim3(RTOT/128, 1), 256, SMT32_BYTES>>>(fh, fl, 64, wch2, wcl2, 64, pq, 128, 64);
    k_gather<<<RTOT/32, 256>>>(pq, idx, hmax, sum, sumsq, 64);
    k_bn_f<<<RTOT/8, 256>>>(hmax, sum, sumsq, ga[1], be[1],
                            c5h, c5l, 64, fh, fl, xx, 64, invKN, 1);

    // ---- layer 3 ----
    k_pair_t32<<<dim3(8, 8, 32), 256, SMT32_BYTES>>>(fh, fl, 64, xx, pd);
    k_topk_w<<<RTOT/8, 256>>>(pd, idx, sum, sumsq);
    k_pq_t32<<<dim3(RTOT/128, 2), 256, SMT32_BYTES>>>(fh, fl, 64, wch3, wcl3, 64, pq, 256, 64);
    k_gather<<<RTOT/32, 256>>>(pq, idx, hmax, sum, sumsq, 128);
    k_bn_f<<<RTOT/8, 256>>>(hmax, sum, sumsq, ga[2], be[2],
                            c5h, c5l, 128, fh, fl, xx, 128, invKN, 1);

    // ---- layer 4 ----
    k_pair_t32<<<dim3(8, 8, 32), 256, SMT32_BYTES>>>(fh, fl, 128, xx, pd);
    k_topk_w<<<RTOT/8, 256>>>(pd, idx, sum, sumsq);
    k_pq_t32<<<dim3(RTOT/128, 4), 256, SMT32_BYTES>>>(fh, fl, 128, wch4, wcl4, 128, pq, 512, 128);
    k_gather<<<RTOT/32, 256>>>(pq, idx, hmax, sum, sumsq, 256);
    k_bn_f<<<RTOT/8, 256>>>(hmax, sum, sumsq, ga[3], be[3],
                            c5h, c5l, 256, fh, fl, xx, 256, invKN, 0);

    // ---- layer 5: GEMM with fused reduction, then BN+lrelu ----
    k_mma5<<<dim3(RTOT/128, 1024/128), 256, SM5_BYTES>>>(c5h, c5l, w5h, w5l, redp, sum5, sumsq5);
    k_final<<<RTOT/256, 256>>>(redp, sum5, sumsq5, ga[4], be[4], (float*)d_out);
}

// round 15
// speedup vs baseline: 1.1223x; 1.1223x over previous
#include <cuda_runtime.h>
#include <cuda_bf16.h>
#include <math.h>
#include <stdint.h>

#define BB 32
#define NN 1024
#define KNN 20
#define RTOT (BB*NN)          // 32768 rows
#define NEG_SLOPE 0.2f
#define EPS 1e-5f

// ---------------- static scratch (allocation-free rule) ----------------
__device__ __align__(256) float g_pd[(size_t)BB*NN*NN];     // 128 MB
__device__ __align__(256) int   g_idx[(size_t)RTOT*KNN];
__device__ __align__(256) float g_pq[(size_t)RTOT*512];     // packed [p|q]
__device__ __align__(256) float g_hmax[(size_t)RTOT*256];
__device__ __align__(256) float g_wc[1024];                 // layer-1 packed W (fp32)
__device__ __align__(256) float g_wch[131072];              // tf32-hi packed W, layers 2-4
__device__ __align__(256) float g_wcl[131072];              // tf32-lo
__device__ __align__(256) float g_fh[(size_t)RTOT*128];     // tf32-hi features
__device__ __align__(256) float g_fl[(size_t)RTOT*128];
__device__ __align__(256) __nv_bfloat16 g_c5h[(size_t)RTOT*512];  // bf16-hi cat
__device__ __align__(256) __nv_bfloat16 g_c5l[(size_t)RTOT*512];  // bf16-lo cat
__device__ __align__(256) float g_xx[RTOT];
__device__ __align__(256) float g_sum[1024];
__device__ __align__(256) float g_sumsq[1024];
__device__ __align__(256) float g_sum5[1024];
__device__ __align__(256) float g_sumsq5[1024];
__device__ __align__(256) float g_redp[BB*8*1024];          // layer-5 partial maxes
__device__ __align__(256) __nv_bfloat16 g_w5h[1024*512];
__device__ __align__(256) __nv_bfloat16 g_w5l[1024*512];

// ---------------- mma helpers ----------------
__device__ __forceinline__ void mma16816(float* c, const uint32_t* a, const uint32_t* b) {
    asm volatile("mma.sync.aligned.m16n8k16.row.col.f32.bf16.bf16.f32 "
        "{%0,%1,%2,%3}, {%4,%5,%6,%7}, {%8,%9}, {%0,%1,%2,%3};"
        : "+f"(c[0]), "+f"(c[1]), "+f"(c[2]), "+f"(c[3])
        : "r"(a[0]), "r"(a[1]), "r"(a[2]), "r"(a[3]), "r"(b[0]), "r"(b[1]));
}
__device__ __forceinline__ void mma1688(float* c, const uint32_t* a, const uint32_t* b) {
    asm volatile("mma.sync.aligned.m16n8k8.row.col.f32.tf32.tf32.f32 "
        "{%0,%1,%2,%3}, {%4,%5,%6,%7}, {%8,%9}, {%0,%1,%2,%3};"
        : "+f"(c[0]), "+f"(c[1]), "+f"(c[2]), "+f"(c[3])
        : "r"(a[0]), "r"(a[1]), "r"(a[2]), "r"(a[3]), "r"(b[0]), "r"(b[1]));
}
__device__ __forceinline__ void split_tf32(float v, uint32_t &hi, uint32_t &lo) {
    asm("cvt.rna.tf32.f32 %0, %1;" : "=r"(hi) : "f"(v));
    float r = v - __uint_as_float(hi);
    asm("cvt.rna.tf32.f32 %0, %1;" : "=r"(lo) : "f"(r));
}

// ---------------- TF32x3 tile engine: 128x128 C tile, 256 threads (round-12 proven) ----
#define ST32 36
#define SMT32_FLOATS (4*128*ST32)
#define SMT32_BYTES  (SMT32_FLOATS*4)

__device__ __forceinline__ void t32_load_pre(const float* __restrict__ Ph,
                                             const float* __restrict__ Pl, int ldp,
                                             int kc, float* sh, float* sl, int tid) {
    #pragma unroll
    for (int it = 0; it < 4; it++) {
        int i = it*256 + tid;
        int row = i >> 3, kq = (i & 7)*4;
        uint4 h = *(const uint4*)(Ph + (size_t)row*ldp + kc + kq);
        uint4 l = *(const uint4*)(Pl + (size_t)row*ldp + kc + kq);
        *(uint4*)((uint32_t*)sh + row*ST32 + kq) = h;
        *(uint4*)((uint32_t*)sl + row*ST32 + kq) = l;
    }
}

__device__ __forceinline__ void t32_tile(const float* __restrict__ Ah_g, const float* __restrict__ Al_g, int lda,
                                         const float* __restrict__ Bh_g, const float* __restrict__ Bl_g, int ldb,
                                         int Kdim,
                                         float* sAh, float* sAl, float* sBh, float* sBl,
                                         int tid, float (&acc)[4][4][4]) {
    int warp = tid >> 5, lane = tid & 31;
    int g = lane >> 2, t = lane & 3;
    int wm = (warp >> 2)*64, wn = (warp & 3)*32;
    for (int kc = 0; kc < Kdim; kc += 32) {
        t32_load_pre(Ah_g, Al_g, lda, kc, sAh, sAl, tid);
        t32_load_pre(Bh_g, Bl_g, ldb, kc, sBh, sBl, tid);
        __syncthreads();
        #pragma unroll
        for (int ks = 0; ks < 32; ks += 8) {
            uint32_t ah[4][4], al[4][4];
            #pragma unroll
            for (int mt = 0; mt < 4; mt++) {
                const uint32_t* bh = (uint32_t*)sAh + (wm + mt*16)*ST32 + ks;
                const uint32_t* bl = (uint32_t*)sAl + (wm + mt*16)*ST32 + ks;
                ah[mt][0] = bh[g*ST32 + t];       ah[mt][1] = bh[(g+8)*ST32 + t];
                ah[mt][2] = bh[g*ST32 + t + 4];   ah[mt][3] = bh[(g+8)*ST32 + t + 4];
                al[mt][0] = bl[g*ST32 + t];       al[mt][1] = bl[(g+8)*ST32 + t];
                al[mt][2] = bl[g*ST32 + t + 4];   al[mt][3] = bl[(g+8)*ST32 + t + 4];
            }
            #pragma unroll
            for (int nt = 0; nt < 4; nt++) {
                const uint32_t* ph = (uint32_t*)sBh + (wn + nt*8 + g)*ST32 + ks;
                const uint32_t* pl = (uint32_t*)sBl + (wn + nt*8 + g)*ST32 + ks;
                uint32_t bh[2] = {ph[t], ph[t+4]};
                uint32_t bl[2] = {pl[t], pl[t+4]};
                #pragma unroll
                for (int mt = 0; mt < 4; mt++) {
                    mma1688(acc[mt][nt], ah[mt], bh);
                    mma1688(acc[mt][nt], ah[mt], bl);
                    mma1688(acc[mt][nt], al[mt], bh);
                }
            }
        }
        __syncthreads();
    }
}

// pairwise distances with SYMMETRY: compute lower-triangle tile (bi >= bj),
// write normal + mirrored (transposed via padded smem) orientations.
__global__ void __launch_bounds__(256)
k_pair_t32(const float* __restrict__ fh, const float* __restrict__ fl, int Kdim,
           const float* __restrict__ xx, float* __restrict__ pd) {
    extern __shared__ float sm32[];
    float* sAh = sm32;
    float* sAl = sm32 + 128*ST32;
    float* sBh = sm32 + 2*128*ST32;
    float* sBl = sm32 + 3*128*ST32;
    int b = blockIdx.z;
    // triangular decode: p -> (bi, bj), bj <= bi, 36 pairs for 8x8 grid
    int p = blockIdx.x;
    int bi = 0;
    while ((bi+1)*(bi+2)/2 <= p) bi++;
    int bj = p - bi*(bi+1)/2;
    int n0 = bi*128, m0 = bj*128;

    const float* Fh = fh + (size_t)b*NN*Kdim;
    const float* Fl = fl + (size_t)b*NN*Kdim;
    const float* xb = xx + b*NN;
    int tid = threadIdx.x;
    float acc[4][4][4];
    #pragma unroll
    for (int i = 0; i < 4; i++)
        #pragma unroll
        for (int j = 0; j < 4; j++)
            #pragma unroll
            for (int r = 0; r < 4; r++) acc[i][j][r] = 0.f;

    t32_tile(Fh + (size_t)n0*Kdim, Fl + (size_t)n0*Kdim, Kdim,
             Fh + (size_t)m0*Kdim, Fl + (size_t)m0*Kdim, Kdim, Kdim,
             sAh, sAl, sBh, sBl, tid, acc);

    int warp = tid >> 5, lane = tid & 31;
    int g = lane >> 2, t = lane & 3;
    int wm = (warp >> 2)*64, wn = (warp & 3)*32;
    float* pb = pd + (size_t)b*NN*NN;
    float* T = sm32;   // reuse: 64 x 132 staged pd tile (33.8 KB)

    #pragma unroll
    for (int half = 0; half < 2; half++) {
        __syncthreads();
        if (wm == half*64) {
            #pragma unroll
            for (int mt = 0; mt < 4; mt++) {
                int rl = mt*16 + g;                 // local row 0..63 (plus +8)
                int n  = n0 + half*64 + rl;
                float xn0 = xb[n], xn1 = xb[n+8];
                #pragma unroll
                for (int nt = 0; nt < 4; nt++) {
                    int c = wn + nt*8 + 2*t;
                    float xm0 = xb[m0 + c], xm1 = xb[m0 + c + 1];
                    T[rl*132 + c]        = 2.f*acc[mt][nt][0] - xn0 - xm0;
                    T[rl*132 + c + 1]    = 2.f*acc[mt][nt][1] - xn0 - xm1;
                    T[(rl+8)*132 + c]    = 2.f*acc[mt][nt][2] - xn1 - xm0;
                    T[(rl+8)*132 + c + 1]= 2.f*acc[mt][nt][3] - xn1 - xm1;
                }
            }
        }
        __syncthreads();
        // normal orientation: rows [n0+half*64, +64), cols [m0, m0+128)
        #pragma unroll
        for (int it = 0; it < 8; it++) {
            int idx = it*256 + tid;                 // 0..2047
            int r = idx >> 5, cq = (idx & 31)*4;
            float4 v = *(const float4*)(T + r*132 + cq);
            *(float4*)(pb + (size_t)(n0 + half*64 + r)*NN + m0 + cq) = v;
        }
        // mirrored orientation (skip on diagonal blocks)
        if (n0 != m0) {
            #pragma unroll
            for (int it = 0; it < 8; it++) {
                int idx = it*256 + tid;
                int c = idx >> 4, rq = (idx & 15)*4;
                float4 v = make_float4(T[rq*132 + c], T[(rq+1)*132 + c],
                                       T[(rq+2)*132 + c], T[(rq+3)*132 + c]);
                *(float4*)(pb + (size_t)(m0 + c)*NN + n0 + half*64 + rq) = v;
            }
        }
    }
}

__global__ void __launch_bounds__(256)
k_pq_t32(const float* __restrict__ fh, const float* __restrict__ fl, int lda,
         const float* __restrict__ wh, const float* __restrict__ wl, int ldb,
         float* __restrict__ Cout, int ldc, int Kdim) {
    extern __shared__ float sm32[];
    float* sAh = sm32;
    float* sAl = sm32 + 128*ST32;
    float* sBh = sm32 + 2*128*ST32;
    float* sBl = sm32 + 3*128*ST32;
    int m0 = blockIdx.x*128, o0 = blockIdx.y*128;
    int tid = threadIdx.x;
    float acc[4][4][4];
    #pragma unroll
    for (int i = 0; i < 4; i++)
        #pragma unroll
        for (int j = 0; j < 4; j++)
            #pragma unroll
            for (int r = 0; r < 4; r++) acc[i][j][r] = 0.f;

    t32_tile(fh + (size_t)m0*lda, fl + (size_t)m0*lda, lda,
             wh + (size_t)o0*ldb, wl + (size_t)o0*ldb, ldb, Kdim,
             sAh, sAl, sBh, sBl, tid, acc);

    int warp = tid >> 5, lane = tid & 31;
    int g = lane >> 2, t = lane & 3;
    int wm = (warp >> 2)*64, wn = (warp & 3)*32;
    #pragma unroll
    for (int mt = 0; mt < 4; mt++) {
        int r = m0 + wm + mt*16 + g;
        #pragma unroll
        for (int nt = 0; nt < 4; nt++) {
            int col = o0 + wn + nt*8 + 2*t;
            *(float2*)(Cout + (size_t)r*ldc + col)     = make_float2(acc[mt][nt][0], acc[mt][nt][1]);
            *(float2*)(Cout + (size_t)(r+8)*ldc + col) = make_float2(acc[mt][nt][2], acc[mt][nt][3]);
        }
    }
}

// ---------------- warp top-20 over 32x32 register tile ----------------
__device__ __forceinline__ void warp_top20(float (&vals)[32], int lane, int* orow) {
    unsigned rm = 0;
    float bv = vals[0]; int bslot = 0;
    #pragma unroll
    for (int j = 1; j < 32; j++) { float v = vals[j]; if (v > bv) { bv = v; bslot = j; } }
    for (int it = 0; it < KNN; it++) {
        float cv = bv;
        int ci = (bslot >= 0) ? (bslot*32 + lane) : 0x7fffffff;
        if (bslot < 0) cv = -INFINITY;
        #pragma unroll
        for (int s = 16; s > 0; s >>= 1) {
            float ov = __shfl_xor_sync(0xffffffffu, cv, s);
            int   oi = __shfl_xor_sync(0xffffffffu, ci, s);
            if (ov > cv || (ov == cv && oi < ci)) { cv = ov; ci = oi; }
        }
        if (lane == 0) orow[it] = ci;
        if ((ci & 31) == lane) {
            rm |= 1u << (ci >> 5);
            bv = -INFINITY; bslot = -1;
            #pragma unroll
            for (int j = 0; j < 32; j++) {
                if (!((rm >> j) & 1u)) {
                    float v = vals[j];
                    if (v > bv) { bv = v; bslot = j; }
                }
            }
        }
    }
}

// ---------------- kernels ----------------

__global__ void k_knn3(const float* __restrict__ x, int* __restrict__ idx,
                       float* __restrict__ sum, float* __restrict__ sumsq,
                       float* __restrict__ sum5, float* __restrict__ sumsq5) {
    __shared__ float sx[NN], sy[NN], sz[NN];
    int b = blockIdx.y;
    const float* xb = x + (size_t)b*NN*3;
    int tid = threadIdx.x;
    if (blockIdx.x == 0 && b == 0) {
        for (int i = tid; i < 1024; i += 256) {
            sum[i] = 0.f; sumsq[i] = 0.f; sum5[i] = 0.f; sumsq5[i] = 0.f;
        }
    }
    for (int i = tid; i < NN; i += 256) {
        sx[i] = xb[i*3+0]; sy[i] = xb[i*3+1]; sz[i] = xb[i*3+2];
    }
    __syncthreads();
    int warp = tid >> 5, lane = tid & 31;
    int n = blockIdx.x*8 + warp;
    float xnx = sx[n], xny = sy[n], xnz = sz[n];
    float xxn = xnx*xnx; xxn += xny*xny; xxn += xnz*xnz;
    float vals[32];
    #pragma unroll
    for (int j = 0; j < 32; j++) {
        int m = j*32 + lane;
        float mx = sx[m], my = sy[m], mz = sz[m];
        float inner = xnx*mx; inner += xny*my; inner += xnz*mz;
        float xxm = mx*mx; xxm += my*my; xxm += mz*mz;
        vals[j] = 2.f*inner - xxn - xxm;
    }
    warp_top20(vals, lane, idx + (size_t)(b*NN + n)*KNN);
}

__global__ void k_topk_w(const float* __restrict__ pd, int* __restrict__ idx,
                         float* __restrict__ sum, float* __restrict__ sumsq) {
    int tid = threadIdx.x;
    if (blockIdx.x == 0) {
        for (int i = tid; i < 1024; i += 256) { sum[i] = 0.f; sumsq[i] = 0.f; }
    }
    int warp = tid >> 5;
    int lane = tid & 31;
    int row = blockIdx.x*8 + warp;
    const float* prow = pd + (size_t)row*NN;
    float vals[32];
    #pragma unroll
    for (int j = 0; j < 32; j++) vals[j] = prow[j*32 + lane];
    warp_top20(vals, lane, idx + (size_t)row*KNN);
}

__global__ void k_wpack(const float* __restrict__ W, int C, int O, float* __restrict__ wc) {
    int i = blockIdx.x*blockDim.x + threadIdx.x;
    if (i >= 2*O*C) return;
    int o2 = i / C, c = i - o2*C;
    if (o2 < O) wc[i] = W[(size_t)o2*2*C + c];
    else {
        int o = o2 - O;
        wc[i] = W[(size_t)o*2*C + C + c] - W[(size_t)o*2*C + c];
    }
}

__global__ void k_wpack_t32(const float* __restrict__ W, int C, int O,
                            float* __restrict__ wh, float* __restrict__ wl) {
    int i = blockIdx.x*blockDim.x + threadIdx.x;
    if (i >= 2*O*C) return;
    int o2 = i / C, c = i - o2*C;
    float v;
    if (o2 < O) v = W[(size_t)o2*2*C + c];
    else {
        int o = o2 - O;
        v = W[(size_t)o*2*C + C + c] - W[(size_t)o*2*C + c];
    }
    uint32_t hi, lo;
    split_tf32(v, hi, lo);
    wh[i] = __uint_as_float(hi);
    wl[i] = __uint_as_float(lo);
}

__global__ void k_cvt_w5(const float* __restrict__ W5, __nv_bfloat16* __restrict__ wh,
                         __nv_bfloat16* __restrict__ wl) {
    int i = blockIdx.x*blockDim.x + threadIdx.x;
    if (i >= 1024*512) return;
    float w = W5[i];
    __nv_bfloat16 h = __float2bfloat16(w);
    wh[i] = h;
    wl[i] = __float2bfloat16(w - __bfloat162float(h));
}

__global__ void k_sgemm(const float* __restrict__ A, int lda,
                        const float* __restrict__ Bw, int ldb,
                        float* __restrict__ Cout, int Kdim, int O) {
    __shared__ float As[16][65], Ws[16][65];
    int tx = threadIdx.x, ty = threadIdx.y;
    int tid = ty*16 + tx;
    int m0 = blockIdx.x*64, o0 = blockIdx.y*64;
    float acc[4][4];
    #pragma unroll
    for (int i = 0; i < 4; i++)
        #pragma unroll
        for (int j = 0; j < 4; j++) acc[i][j] = 0.f;
    for (int k0 = 0; k0 < Kdim; k0 += 16) {
        #pragma unroll
        for (int r = 0; r < 4; r++) {
            int i  = tid + r*256;
            int kk = i & 15, mm = i >> 4;
            As[kk][mm] = (k0+kk < Kdim) ? A[(size_t)(m0+mm)*lda + k0+kk] : 0.f;
            Ws[kk][mm] = (k0+kk < Kdim) ? Bw[(size_t)(o0+mm)*ldb + k0+kk] : 0.f;
        }
        __syncthreads();
        #pragma unroll
        for (int kk = 0; kk < 16; kk++) {
            float a[4], bfr[4];
            #pragma unroll
            for (int i = 0; i < 4; i++) a[i] = As[kk][ty*4 + i];
            #pragma unroll
            for (int j = 0; j < 4; j++) bfr[j] = Ws[kk][tx*4 + j];
            #pragma unroll
            for (int i = 0; i < 4; i++)
                #pragma unroll
                for (int j = 0; j < 4; j++) acc[i][j] += a[i]*bfr[j];
        }
        __syncthreads();
    }
    #pragma unroll
    for (int i = 0; i < 4; i++)
        #pragma unroll
        for (int j = 0; j < 4; j++)
            Cout[(size_t)(m0 + ty*4 + i)*O + o0 + tx*4 + j] = acc[i][j];
}

// ---------------- layer-5 GEMM with FUSED max/sum/sumsq reduction ----
#define KC5 64
#define SA5 72
#define SM5_TILE (128*SA5)
#define SM5_BYTES (4*SM5_TILE*2)

__global__ void __launch_bounds__(256, 1)
k_mma5(const __nv_bfloat16* __restrict__ c5h, const __nv_bfloat16* __restrict__ c5l,
       const __nv_bfloat16* __restrict__ w5h, const __nv_bfloat16* __restrict__ w5l,
       float* __restrict__ redp, float* __restrict__ sum5, float* __restrict__ sumsq5) {
    extern __shared__ __nv_bfloat16 sm[];
    __nv_bfloat16* Ah = sm;
    __nv_bfloat16* Al = sm + SM5_TILE;
    __nv_bfloat16* Bh = sm + 2*SM5_TILE;
    __nv_bfloat16* Bl = sm + 3*SM5_TILE;

    int tid = threadIdx.x;
    int warp = tid >> 5, lane = tid & 31;
    int g = lane >> 2, t = lane & 3;
    int m0 = blockIdx.x*128, o0 = blockIdx.y*128;
    int wm = (warp >> 2)*64;
    int wn = (warp & 3)*32;

    float acc[4][4][4];
    #pragma unroll
    for (int i = 0; i < 4; i++)
        #pragma unroll
        for (int j = 0; j < 4; j++)
            #pragma unroll
            for (int r = 0; r < 4; r++) acc[i][j][r] = 0.f;

    for (int kc = 0; kc < 512; kc += KC5) {
        #pragma unroll
        for (int it = 0; it < 4; it++) {
            int i = it*256 + tid;
            int row = i >> 3, kq = (i & 7)*8;
            uint4 h = *(const uint4*)(c5h + (size_t)(m0+row)*512 + kc + kq);
            uint4 l = *(const uint4*)(c5l + (size_t)(m0+row)*512 + kc + kq);
            *(uint4*)(Ah + row*SA5 + kq) = h;
            *(uint4*)(Al + row*SA5 + kq) = l;
        }
        #pragma unroll
        for (int it = 0; it < 4; it++) {
            int i = it*256 + tid;
            int row = i >> 3, kq = (i & 7)*8;
            uint4 h = *(const uint4*)(w5h + (size_t)(o0+row)*512 + kc + kq);
            uint4 l = *(const uint4*)(w5l + (size_t)(o0+row)*512 + kc + kq);
            *(uint4*)(Bh + row*SA5 + kq) = h;
            *(uint4*)(Bl + row*SA5 + kq) = l;
        }
        __syncthreads();

        #pragma unroll
        for (int ks = 0; ks < KC5; ks += 16) {
            uint32_t ah[4][4], al[4][4];
            #pragma unroll
            for (int mt = 0; mt < 4; mt++) {
                int r = wm + mt*16;
                ah[mt][0] = *(const uint32_t*)(Ah + (r+g  )*SA5 + ks + 2*t);
                ah[mt][1] = *(const uint32_t*)(Ah + (r+g+8)*SA5 + ks + 2*t);
                ah[mt][2] = *(const uint32_t*)(Ah + (r+g  )*SA5 + ks + 2*t + 8);
                ah[mt][3] = *(const uint32_t*)(Ah + (r+g+8)*SA5 + ks + 2*t + 8);
                al[mt][0] = *(const uint32_t*)(Al + (r+g  )*SA5 + ks + 2*t);
                al[mt][1] = *(const uint32_t*)(Al + (r+g+8)*SA5 + ks + 2*t);
                al[mt][2] = *(const uint32_t*)(Al + (r+g  )*SA5 + ks + 2*t + 8);
                al[mt][3] = *(const uint32_t*)(Al + (r+g+8)*SA5 + ks + 2*t + 8);
            }
            #pragma unroll
            for (int nt = 0; nt < 4; nt++) {
                int nr = wn + nt*8 + g;
                uint32_t bh[2], bl[2];
                bh[0] = *(const uint32_t*)(Bh + nr*SA5 + ks + 2*t);
                bh[1] = *(const uint32_t*)(Bh + nr*SA5 + ks + 2*t + 8);
                bl[0] = *(const uint32_t*)(Bl + nr*SA5 + ks + 2*t);
                bl[1] = *(const uint32_t*)(Bl + nr*SA5 + ks + 2*t + 8);
                #pragma unroll
                for (int mt = 0; mt < 4; mt++) {
                    mma16816(acc[mt][nt], ah[mt], bh);
                    mma16816(acc[mt][nt], ah[mt], bl);
                    mma16816(acc[mt][nt], al[mt], bh);
                }
            }
        }
        __syncthreads();
    }

    // fused reduction over this block's 128 rows x 128 cols
    float cmax[4][2], csum[4][2], csq[4][2];
    #pragma unroll
    for (int nt = 0; nt < 4; nt++)
        #pragma unroll
        for (int p = 0; p < 2; p++) { cmax[nt][p] = -INFINITY; csum[nt][p] = 0.f; csq[nt][p] = 0.f; }
    #pragma unroll
    for (int mt = 0; mt < 4; mt++)
        #pragma unroll
        for (int nt = 0; nt < 4; nt++) {
            float v0 = acc[mt][nt][0], v1 = acc[mt][nt][1];
            float v2 = acc[mt][nt][2], v3 = acc[mt][nt][3];
            cmax[nt][0] = fmaxf(cmax[nt][0], fmaxf(v0, v2));
            cmax[nt][1] = fmaxf(cmax[nt][1], fmaxf(v1, v3));
            csum[nt][0] += v0 + v2;  csum[nt][1] += v1 + v3;
            csq[nt][0]  += v0*v0 + v2*v2;  csq[nt][1] += v1*v1 + v3*v3;
        }
    #pragma unroll
    for (int s = 4; s <= 16; s <<= 1) {
        #pragma unroll
        for (int nt = 0; nt < 4; nt++)
            #pragma unroll
            for (int p = 0; p < 2; p++) {
                cmax[nt][p] = fmaxf(cmax[nt][p], __shfl_xor_sync(0xffffffffu, cmax[nt][p], s));
                csum[nt][p] += __shfl_xor_sync(0xffffffffu, csum[nt][p], s);
                csq[nt][p]  += __shfl_xor_sync(0xffffffffu, csq[nt][p], s);
            }
    }
    float* rr = (float*)sm;
    float* rmax = rr;
    float* rsum = rr + 256;
    float* rsq  = rr + 512;
    int wrow = warp >> 2;
    if (g == 0) {
        #pragma unroll
        for (int nt = 0; nt < 4; nt++)
            #pragma unroll
            for (int p = 0; p < 2; p++) {
                int col = wn + nt*8 + 2*t + p;
                rmax[wrow*128 + col] = cmax[nt][p];
                rsum[wrow*128 + col] = csum[nt][p];
                rsq[wrow*128 + col]  = csq[nt][p];
            }
    }
    __syncthreads();
    if (tid < 128) {
        float m = fmaxf(rmax[tid], rmax[128 + tid]);
        float s = rsum[tid] + rsum[128 + tid];
        float q = rsq[tid] + rsq[128 + tid];
        int b = blockIdx.x >> 3, mb = blockIdx.x & 7;
        redp[((size_t)b*8 + mb)*1024 + o0 + tid] = m;
        atomicAdd(&sum5[o0 + tid], s);
        atomicAdd(&sumsq5[o0 + tid], q);
    }
}

// gather: 256 threads, float4 column groups, 32 rows/block
__global__ void __launch_bounds__(256)
k_gather(const float* __restrict__ pq, const int* __restrict__ idx,
         float* __restrict__ hmax,
         float* __restrict__ sum, float* __restrict__ sumsq, int O) {
    int tid = threadIdx.x;
    int oq4 = O >> 2;
    int nr = 256/oq4;
    int rsub = tid / oq4;
    int cg = tid - rsub*oq4;
    int r0 = blockIdx.x*32;
    int b = r0 >> 10;
    int ld = 2*O;
    __shared__ int sidx[32*KNN];
    __shared__ float4 ssum[256], ssq[256];
    for (int i = tid; i < 32*KNN; i += 256) sidx[i] = idx[(size_t)r0*KNN + i];
    __syncthreads();
    const float* pb = pq + (size_t)b*NN*ld;
    float4 s  = make_float4(0.f, 0.f, 0.f, 0.f);
    float4 s2 = make_float4(0.f, 0.f, 0.f, 0.f);
    for (int n = rsub; n < 32; n += nr) {
        int row = r0 + n;
        float4 cq = *(const float4*)(pq + (size_t)row*ld + O + cg*4);
        float4 mx = make_float4(-INFINITY, -INFINITY, -INFINITY, -INFINITY);
        #pragma unroll
        for (int k = 0; k < KNN; k++) {
            float4 v = *(const float4*)(pb + (size_t)sidx[n*KNN + k]*ld + cg*4);
            mx.x = fmaxf(mx.x, v.x); mx.y = fmaxf(mx.y, v.y);
            mx.z = fmaxf(mx.z, v.z); mx.w = fmaxf(mx.w, v.w);
            float hx = v.x + cq.x, hy = v.y + cq.y, hz = v.z + cq.z, hw = v.w + cq.w;
            s.x += hx; s.y += hy; s.z += hz; s.w += hw;
            s2.x += hx*hx; s2.y += hy*hy; s2.z += hz*hz; s2.w += hw*hw;
        }
        *(float4*)(hmax + (size_t)row*O + cg*4) =
            make_float4(mx.x + cq.x, mx.y + cq.y, mx.z + cq.z, mx.w + cq.w);
    }
    ssum[tid] = s; ssq[tid] = s2;
    __syncthreads();
    if (rsub == 0) {
        for (int j = 1; j < nr; j++) {
            float4 a = ssum[j*oq4 + cg], q = ssq[j*oq4 + cg];
            s.x += a.x; s.y += a.y; s.z += a.z; s.w += a.w;
            s2.x += q.x; s2.y += q.y; s2.z += q.z; s2.w += q.w;
        }
        atomicAdd(&sum[cg*4+0], s.x);  atomicAdd(&sum[cg*4+1], s.y);
        atomicAdd(&sum[cg*4+2], s.z);  atomicAdd(&sum[cg*4+3], s.w);
        atomicAdd(&sumsq[cg*4+0], s2.x); atomicAdd(&sumsq[cg*4+1], s2.y);
        atomicAdd(&sumsq[cg*4+2], s2.z); atomicAdd(&sumsq[cg*4+3], s2.w);
    }
}

__global__ void k_bn_f(const float* __restrict__ hmax, const float* __restrict__ sum,
                       const float* __restrict__ sumsq,
                       const float* __restrict__ gamma, const float* __restrict__ beta,
                       __nv_bfloat16* __restrict__ c5h, __nv_bfloat16* __restrict__ c5l, int coff,
                       float* __restrict__ fh, float* __restrict__ fl, float* __restrict__ xx,
                       int O, float invCnt, int wantNext) {
    int warp = threadIdx.x >> 5, lane = threadIdx.x & 31;
    int row = blockIdx.x*8 + warp;
    float s2 = 0.f;
    for (int o = lane; o < O; o += 32) {
        float mean = sum[o]*invCnt;
        float var  = sumsq[o]*invCnt - mean*mean;
        float hn = (hmax[(size_t)row*O + o] - mean)*rsqrtf(var + EPS)*gamma[o] + beta[o];
        hn = hn >= 0.f ? hn : NEG_SLOPE*hn;
        __nv_bfloat16 h = __float2bfloat16(hn);
        c5h[(size_t)row*512 + coff + o] = h;
        c5l[(size_t)row*512 + coff + o] = __float2bfloat16(hn - __bfloat162float(h));
        if (wantNext) {
            uint32_t thi, tlo;
            split_tf32(hn, thi, tlo);
            fh[(size_t)row*O + o] = __uint_as_float(thi);
            fl[(size_t)row*O + o] = __uint_as_float(tlo);
            s2 += hn*hn;
        }
    }
    if (wantNext) {
        #pragma unroll
        for (int s = 16; s > 0; s >>= 1) s2 += __shfl_xor_sync(0xffffffffu, s2, s);
        if (lane == 0) xx[row] = s2;
    }
}

__global__ void k_final(const float* __restrict__ redp, const float* __restrict__ sum,
                        const float* __restrict__ sumsq,
                        const float* __restrict__ gamma, const float* __restrict__ beta,
                        float* __restrict__ out) {
    int e = blockIdx.x*blockDim.x + threadIdx.x;   // 32768
    int b = e >> 10, o = e & 1023;
    float mx = -INFINITY;
    #pragma unroll
    for (int z = 0; z < 8; z++) mx = fmaxf(mx, redp[((size_t)b*8 + z)*1024 + o]);
    float invCnt = 1.f/32768.f;
    float mean = sum[o]*invCnt;
    float var  = sumsq[o]*invCnt - mean*mean;
    float hn = (mx - mean)*rsqrtf(var + EPS)*gamma[o] + beta[o];
    out[e] = hn >= 0.f ? hn : NEG_SLOPE*hn;
}

// ---------------- host driver ----------------

extern "C" void kernel_launch(void* const* d_in, const int* in_sizes, int n_in,
                              void* d_out, int out_size) {
    const float* x = (const float*)d_in[0];
    const float* W[5]; const float* ga[5]; const float* be[5];
    for (int i = 0; i < 5; i++) {
        W[i]  = (const float*)d_in[1 + 3*i];
        ga[i] = (const float*)d_in[2 + 3*i];
        be[i] = (const float*)d_in[3 + 3*i];
    }

    float *pd, *pq, *hmax, *wc, *wch, *wcl, *fh, *fl, *xx, *sum, *sumsq, *sum5, *sumsq5, *redp;
    __nv_bfloat16 *c5h, *c5l, *w5h, *w5l;
    int *idx;
    cudaGetSymbolAddress((void**)&pd,    g_pd);
    cudaGetSymbolAddress((void**)&idx,   g_idx);
    cudaGetSymbolAddress((void**)&pq,    g_pq);
    cudaGetSymbolAddress((void**)&hmax,  g_hmax);
    cudaGetSymbolAddress((void**)&wc,    g_wc);
    cudaGetSymbolAddress((void**)&wch,   g_wch);
    cudaGetSymbolAddress((void**)&wcl,   g_wcl);
    cudaGetSymbolAddress((void**)&fh,    g_fh);
    cudaGetSymbolAddress((void**)&fl,    g_fl);
    cudaGetSymbolAddress((void**)&xx,    g_xx);
    cudaGetSymbolAddress((void**)&sum,   g_sum);
    cudaGetSymbolAddress((void**)&sumsq, g_sumsq);
    cudaGetSymbolAddress((void**)&sum5,  g_sum5);
    cudaGetSymbolAddress((void**)&sumsq5, g_sumsq5);
    cudaGetSymbolAddress((void**)&redp,  g_redp);
    cudaGetSymbolAddress((void**)&c5h,   g_c5h);
    cudaGetSymbolAddress((void**)&c5l,   g_c5l);
    cudaGetSymbolAddress((void**)&w5h,   g_w5h);
    cudaGetSymbolAddress((void**)&w5l,   g_w5l);

    cudaFuncSetAttribute(k_mma5, cudaFuncAttributeMaxDynamicSharedMemorySize, SM5_BYTES);
    cudaFuncSetAttribute(k_pair_t32, cudaFuncAttributeMaxDynamicSharedMemorySize, SMT32_BYTES);
    cudaFuncSetAttribute(k_pq_t32, cudaFuncAttributeMaxDynamicSharedMemorySize, SMT32_BYTES);

    float* wch2 = wch;           float* wcl2 = wcl;
    float* wch3 = wch + 8192;    float* wcl3 = wcl + 8192;
    float* wch4 = wch + 24576;   float* wcl4 = wcl + 24576;

    const float invKN = 1.f/((float)RTOT*KNN);

    // ---- layer 1 (C=3) ----
    k_wpack<<<(2*64*3 + 255)/256, 256>>>(W[0], 3, 64, wc);
    k_knn3<<<dim3(128, 32), 256>>>(x, idx, sum, sumsq, sum5, sumsq5);
    k_sgemm<<<dim3(RTOT/64, 2), dim3(16,16)>>>(x, 3, wc, 3, pq, 3, 128);
    k_gather<<<RTOT/32, 256>>>(pq, idx, hmax, sum, sumsq, 64);
    k_bn_f<<<RTOT/8, 256>>>(hmax, sum, sumsq, ga[0], be[0],
                            c5h, c5l, 0, fh, fl, xx, 64, invKN, 1);

    // ---- layer 2 ----
    k_pair_t32<<<dim3(36, 1, 32), 256, SMT32_BYTES>>>(fh, fl, 64, xx, pd);
    k_wpack_t32<<<(2*64*64  + 255)/256, 256>>>(W[1], 64,  64,  wch2, wcl2);
    k_wpack_t32<<<(2*128*64 + 255)/256, 256>>>(W[2], 64,  128, wch3, wcl3);
    k_wpack_t32<<<(2*256*128+ 255)/256, 256>>>(W[3], 128, 256, wch4, wcl4);
    k_cvt_w5<<<(1024*512 + 255)/256, 256>>>(W[4], w5h, w5l);
    k_topk_w<<<RTOT/8, 256>>>(pd, idx, sum, sumsq);
    k_pq_t32<<<dim3(RTOT/128, 1), 256, SMT32_BYTES>>>(fh, fl, 64, wch2, wcl2, 64, pq, 128, 64);
    k_gather<<<RTOT/32, 256>>>(pq, idx, hmax, sum, sumsq, 64);
    k_bn_f<<<RTOT/8, 256>>>(hmax, sum, sumsq, ga[1], be[1],
                            c5h, c5l, 64, fh, fl, xx, 64, invKN, 1);

    // ---- layer 3 ----
    k_pair_t32<<<dim3(36, 1, 32), 256, SMT32_BYTES>>>(fh, fl, 64, xx, pd);
    k_topk_w<<<RTOT/8, 256>>>(pd, idx, sum, sumsq);
    k_pq_t32<<<dim3(RTOT/128, 2), 256, SMT32_BYTES>>>(fh, fl, 64, wch3, wcl3, 64, pq, 256, 64);
    k_gather<<<RTOT/32, 256>>>(pq, idx, hmax, sum, sumsq, 128);
    k_bn_f<<<RTOT/8, 256>>>(hmax, sum, sumsq, ga[2], be[2],
                            c5h, c5l, 128, fh, fl, xx, 128, invKN, 1);

    // ---- layer 4 ----
    k_pair_t32<<<dim3(36, 1, 32), 256, SMT32_BYTES>>>(fh, fl, 128, xx, pd);
    k_topk_w<<<RTOT/8, 256>>>(pd, idx, sum, sumsq);
    k_pq_t32<<<dim3(RTOT/128, 4), 256, SMT32_BYTES>>>(fh, fl, 128, wch4, wcl4, 128, pq, 512, 128);
    k_gather<<<RTOT/32, 256>>>(pq, idx, hmax, sum, sumsq, 256);
    k_bn_f<<<RTOT/8, 256>>>(hmax, sum, sumsq, ga[3], be[3],
                            c5h, c5l, 256, fh, fl, xx, 256, invKN, 0);

    // ---- layer 5: GEMM with fused reduction, then BN+lrelu ----
    k_mma5<<<dim3(RTOT/128, 1024/128), 256, SM5_BYTES>>>(c5h, c5l, w5h, w5l, redp, sum5, sumsq5);
    k_final<<<RTOT/256, 256>>>(redp, sum5, sumsq5, ga[4], be[4], (float*)d_out);
}